// round 7
// baseline (speedup 1.0000x reference)
#include <cuda_runtime.h>
#include <cuda_fp16.h>
#include <cstdint>

static constexpr int NI = 64;     // items (K)
static constexpr int NH = 256;    // hidden units (N)
static constexpr int TM = 256;    // rows per block (4 warps x 64 rows)
#define ARB_EPS  3e-3f
#define LO_SCALE 2048.0f
#define LO_INV   4.8828125e-4f    // 2^-11

// ---- smem layout (bytes) ----
static constexpr int OFF_WH   = 0;       // 256 x 64 f16 swizzled = 32768
static constexpr int OFF_WL   = 32768;   //                       = 32768
static constexpr int OFF_W0   = 65536;   // 256 f32               = 1024
static constexpr int OFF_CAND = 66560;   // 256 rows x 4 x 8B     = 8192
static constexpr int SMEM_TOTAL = 74752;

// Pre-converted W (swizzled f16 hi/lo), written by prep kernel
__device__ __align__(16) uint32_t g_W16[2][8192];   // 2 x 32768 B

__device__ __forceinline__ uint32_t smem_u32(const void* p) {
    uint32_t a;
    asm("{ .reg .u64 t; cvta.to.shared.u64 t, %1; cvt.u32.u64 %0, t; }" : "=r"(a) : "l"(p));
    return a;
}
__device__ __forceinline__ uint32_t sw128(uint32_t off) { return off ^ ((off >> 3) & 0x70); }

__device__ __forceinline__ void ldsm_x4(uint32_t* r, uint32_t addr) {
    asm volatile("ldmatrix.sync.aligned.m8n8.x4.shared.b16 {%0,%1,%2,%3}, [%4];"
                 : "=r"(r[0]), "=r"(r[1]), "=r"(r[2]), "=r"(r[3]) : "r"(addr));
}
__device__ __forceinline__ void mma16816(float* c, const uint32_t* a, const uint32_t* b) {
    asm volatile("mma.sync.aligned.m16n8k16.row.col.f32.f16.f16.f32 "
                 "{%0,%1,%2,%3}, {%4,%5,%6,%7}, {%8,%9}, {%0,%1,%2,%3};"
                 : "+f"(c[0]), "+f"(c[1]), "+f"(c[2]), "+f"(c[3])
                 : "r"(a[0]), "r"(a[1]), "r"(a[2]), "r"(a[3]), "r"(b[0]), "r"(b[1]));
}

// float2 -> packed f16 hi pair + scaled f16 lo pair
__device__ __forceinline__ void cvt2(float a, float b, uint32_t& hi, uint32_t& lo) {
    __half2 hh = __floats2half2_rn(a, b);
    float2 bk = __half22float2(hh);
    __half2 ll = __floats2half2_rn((a - bk.x) * LO_SCALE, (b - bk.y) * LO_SCALE);
    hi = reinterpret_cast<uint32_t&>(hh);
    lo = reinterpret_cast<uint32_t&>(ll);
}

// pack 8 floats -> uint4 hi + uint4 lo (prep kernel)
__device__ __forceinline__ void convert8(const float* f, uint4& hi, uint4& lo) {
    cvt2(f[0], f[1], hi.x, lo.x);
    cvt2(f[2], f[3], hi.y, lo.y);
    cvt2(f[4], f[5], hi.z, lo.z);
    cvt2(f[6], f[7], hi.w, lo.w);
}

// Reference-order dot: single fp32 FMA chain, ascending k.
__device__ __forceinline__ float dot_seq(const float* __restrict__ Vrow,
                                         const float* __restrict__ Wrow) {
    float acc = 0.0f;
    #pragma unroll
    for (int q = 0; q < 16; q++) {
        float4 v = __ldg(reinterpret_cast<const float4*>(Vrow) + q);
        float4 w = __ldg(reinterpret_cast<const float4*>(Wrow) + q);
        acc = __fmaf_rn(v.x, w.x, acc);
        acc = __fmaf_rn(v.y, w.y, acc);
        acc = __fmaf_rn(v.z, w.z, acc);
        acc = __fmaf_rn(v.w, w.w, acc);
    }
    return acc;
}

// value -> sortable key with (255-h) embedded in low 8 mantissa bits
__device__ __forceinline__ float make_key(float v, int h) {
    uint32_t b = (__float_as_uint(v) & 0xFFFFFF00u) | (uint32_t)(255 - h);
    return __uint_as_float(b);
}
__device__ __forceinline__ int key_h(float k) {
    return 255 - (int)(__float_as_uint(k) & 0xFFu);
}

// ---- prep: convert W to swizzled f16 hi/lo once ----
__global__ void prep_W_kernel(const float* __restrict__ W) {
    const int r = threadIdx.x;            // 256 threads, one W row each
    float f[8];
    #pragma unroll 1
    for (int q = 0; q < 8; q++) {
        *reinterpret_cast<float4*>(f)     = __ldg(reinterpret_cast<const float4*>(W + r * NI) + 2 * q);
        *reinterpret_cast<float4*>(f + 4) = __ldg(reinterpret_cast<const float4*>(W + r * NI) + 2 * q + 1);
        uint4 hi, lo;
        convert8(f, hi, lo);
        const uint32_t off = sw128((uint32_t)r * 128 + q * 16);
        *reinterpret_cast<uint4*>(reinterpret_cast<char*>(g_W16[0]) + off) = hi;
        *reinterpret_cast<uint4*>(reinterpret_cast<char*>(g_W16[1]) + off) = lo;
    }
}

__global__ __launch_bounds__(128, 2)
void rochet_mma_kernel(const float* __restrict__ V,
                       const float* __restrict__ W,
                       const float* __restrict__ w0,
                       float* __restrict__ alloc_out,
                       float* __restrict__ pay_out,
                       int B)
{
    extern __shared__ char smem[];
    const uint32_t sbase = smem_u32(smem);
    const int tid = threadIdx.x;
    const int w   = tid >> 5;         // 4 warps
    const int l   = tid & 31;
    float* w0s = reinterpret_cast<float*>(smem + OFF_W0);

    // ---- stage W (pre-converted + swizzled) and w0 ----
    {
        const uint4* src = reinterpret_cast<const uint4*>(g_W16);
        uint4* dst = reinterpret_cast<uint4*>(smem + OFF_WH);
        #pragma unroll
        for (int i = 0; i < 32; i++) dst[tid + 128 * i] = src[tid + 128 * i];
        w0s[tid] = w0[tid];
        w0s[tid + 128] = w0[tid + 128];
    }

    // ---- build A fragments directly from gmem: 4 mtiles (64 rows/warp) ----
    const long long base = (long long)blockIdx.x * TM;
    uint32_t ah[4][4][4], al[4][4][4];
    {
        const int r0 = w * 64 + (l >> 2);
        const int k0 = (l & 3) * 2;
        #pragma unroll
        for (int mt = 0; mt < 4; mt++)
            #pragma unroll
            for (int j = 0; j < 4; j++) {
                const long long row = base + r0 + mt * 16 + (j & 1) * 8;
                const int kb = k0 + (j >> 1) * 8;
                if (row < (long long)B) {
                    const float2* p = reinterpret_cast<const float2*>(V + row * NI + kb);
                    #pragma unroll
                    for (int ks = 0; ks < 4; ks++) {
                        const float2 v = __ldg(p + ks * 8);   // +16 floats per kstep
                        cvt2(v.x, v.y, ah[mt][ks][j], al[mt][ks][j]);
                    }
                } else {
                    #pragma unroll
                    for (int ks = 0; ks < 4; ks++) { ah[mt][ks][j] = 0u; al[mt][ks][j] = 0u; }
                }
            }
    }
    __syncthreads();

    // ---- main loop over 32 n-tiles ----
    float m1[8], m2[8];
    #pragma unroll
    for (int t = 0; t < 8; t++) { m1[t] = -3.4e38f; m2[t] = -3.4e38f; }

    // ldsm_x4 lane map: lanes 0-7 -> ks k[0:8), 8-15 -> ks k[8:16),
    //                   16-23 -> ks+1 k[0:8), 24-31 -> ks+1 k[8:16)
    const uint32_t bro4 = (uint32_t)(l & 7) * 128 + (uint32_t)((l >> 3) & 3) * 16;
    const int colb = 2 * (l & 3);

    #pragma unroll 2
    for (int nt = 0; nt < 32; nt++) {
        uint32_t bh[4][2], bl[4][2];
        #pragma unroll
        for (int kp = 0; kp < 2; kp++) {
            const uint32_t off = sw128((uint32_t)nt * 1024 + bro4 + kp * 64);
            uint32_t rh[4], rl[4];
            ldsm_x4(rh, sbase + OFF_WH + off);
            ldsm_x4(rl, sbase + OFF_WL + off);
            bh[2*kp][0] = rh[0]; bh[2*kp][1] = rh[1];
            bh[2*kp+1][0] = rh[2]; bh[2*kp+1][1] = rh[3];
            bl[2*kp][0] = rl[0]; bl[2*kp][1] = rl[1];
            bl[2*kp+1][0] = rl[2]; bl[2*kp+1][1] = rl[3];
        }
        const int hbase = nt * 8 + colb;
        const float2 w0p = *reinterpret_cast<const float2*>(smem + OFF_W0 + hbase * 4);

        #pragma unroll
        for (int mt = 0; mt < 4; mt++) {
            float c[4] = {0.f, 0.f, 0.f, 0.f};
            float d[4] = {0.f, 0.f, 0.f, 0.f};
            #pragma unroll
            for (int ks = 0; ks < 4; ks++) mma16816(c, ah[mt][ks], bh[ks]);
            #pragma unroll
            for (int ks = 0; ks < 4; ks++) mma16816(d, ah[mt][ks], bl[ks]);
            #pragma unroll
            for (int ks = 0; ks < 4; ks++) mma16816(d, al[mt][ks], bh[ks]);

            const float k0 = make_key(__fmaf_rn(LO_INV, d[0], c[0]) + w0p.x, hbase);
            const float k1 = make_key(__fmaf_rn(LO_INV, d[1], c[1]) + w0p.y, hbase + 1);
            const float k2 = make_key(__fmaf_rn(LO_INV, d[2], c[2]) + w0p.x, hbase);
            const float k3 = make_key(__fmaf_rn(LO_INV, d[3], c[3]) + w0p.y, hbase + 1);
            const int s0 = 2 * mt, s1 = 2 * mt + 1;
            float t0 = fminf(m1[s0], k0); m1[s0] = fmaxf(m1[s0], k0); m2[s0] = fmaxf(m2[s0], t0);
            float t1 = fminf(m1[s0], k1); m1[s0] = fmaxf(m1[s0], k1); m2[s0] = fmaxf(m2[s0], t1);
            float t2 = fminf(m1[s1], k2); m1[s1] = fmaxf(m1[s1], k2); m2[s1] = fmaxf(m2[s1], t2);
            float t3 = fminf(m1[s1], k3); m1[s1] = fmaxf(m1[s1], k3); m2[s1] = fmaxf(m2[s1], t3);
        }
    }

    // ---- publish per-lane top-2 keys: cand[row_in_cta][l&3] ----
    #pragma unroll
    for (int mt = 0; mt < 4; mt++)
        #pragma unroll
        for (int rh = 0; rh < 2; rh++) {
            const int rc = w * 64 + mt * 16 + rh * 8 + (l >> 2);
            const int st = 2 * mt + rh;
            float2 pk = make_float2(m1[st], m2[st]);
            *reinterpret_cast<float2*>(smem + OFF_CAND + (rc * 4 + (l & 3)) * 8) = pk;
        }
    __syncthreads();

    // ---- epilogue: thread tid handles rows tid and tid+128 ----
    #pragma unroll 1
    for (int half = 0; half < 2; half++) {
        const int rc = tid + half * 128;
        const long long row = base + rc;
        if (row >= (long long)B) break;

        float ck[8];
        #pragma unroll
        for (int q = 0; q < 4; q++) {
            const float2 pk = *reinterpret_cast<const float2*>(smem + OFF_CAND + (rc * 4 + q) * 8);
            ck[2 * q] = pk.x; ck[2 * q + 1] = pk.y;
        }
        float kbest = ck[0];
        #pragma unroll
        for (int q = 1; q < 8; q++) kbest = fmaxf(kbest, ck[q]);
        const int h1 = key_h(kbest);

        const float* Vrow = V + row * NI;
        float bestdot = dot_seq(Vrow, W + h1 * NI);
        float best = bestdot + w0s[h1];
        int bi = h1;
        const float thr = kbest - ARB_EPS;
        #pragma unroll 1
        for (int q = 0; q < 8; q++) {
            const int hq = key_h(ck[q]);
            if (ck[q] >= thr && hq != h1) {
                const float dd = dot_seq(Vrow, W + hq * NI);
                const float s = dd + w0s[hq];
                if (s > best || (s == best && hq < bi)) { best = s; bi = hq; bestdot = dd; }
            }
        }

        float* orow = alloc_out + row * NI;
        if (best > 0.0f) {
            const float4* wr = reinterpret_cast<const float4*>(W + bi * NI);
            #pragma unroll
            for (int q = 0; q < 16; q++) {
                float4 wv = __ldg(wr + q);
                wv.x = fminf(fmaxf(wv.x, 0.f), 1.f);
                wv.y = fminf(fmaxf(wv.y, 0.f), 1.f);
                wv.z = fminf(fmaxf(wv.z, 0.f), 1.f);
                wv.w = fminf(fmaxf(wv.w, 0.f), 1.f);
                reinterpret_cast<float4*>(orow)[q] = wv;
            }
            const float p = bestdot - best;
            pay_out[row] = p > 0.0f ? p : 0.0f;
        } else {
            const float4 z = make_float4(0.f, 0.f, 0.f, 0.f);
            #pragma unroll
            for (int q = 0; q < 16; q++) reinterpret_cast<float4*>(orow)[q] = z;
            pay_out[row] = 0.0f;
        }
    }
}

extern "C" void kernel_launch(void* const* d_in, const int* in_sizes, int n_in,
                              void* d_out, int out_size)
{
    const float* V  = (const float*)d_in[0];   // [B, 64]
    const float* W  = (const float*)d_in[1];   // [256, 64]
    const float* w0 = (const float*)d_in[2];   // [256]
    const int B = in_sizes[0] / NI;

    float* alloc_out = (float*)d_out;                          // [B, 64]
    float* pay_out   = (float*)d_out + (long long)B * NI;      // [B]

    cudaFuncSetAttribute(rochet_mma_kernel,
                         cudaFuncAttributeMaxDynamicSharedMemorySize, SMEM_TOTAL);

    prep_W_kernel<<<1, 256>>>(W);
    const int grid = (B + TM - 1) / TM;
    rochet_mma_kernel<<<grid, 128, SMEM_TOTAL>>>(V, W, w0, alloc_out, pay_out, B);
}

// round 12
// speedup vs baseline: 1.4277x; 1.4277x over previous
#include <cuda_runtime.h>
#include <cuda_fp16.h>
#include <cstdint>

static constexpr int NI = 64;     // items (K)
static constexpr int NH = 256;    // hidden units (N)
static constexpr int TM = 256;    // rows per block (8 warps x 32 rows)
#define ARB_EPS  4e-3f
#define LO_SCALE 2048.0f
#define LO_INV   4.8828125e-4f    // 2^-11

// ---- smem layout (bytes) ----
static constexpr int OFF_WH   = 0;       // 256 x 64 f16 swizzled = 32768
static constexpr int OFF_W0   = 32768;   // 256 f32               = 1024
static constexpr int OFF_CAND = 33792;   // 256 rows x 4 x 8B     = 8192
static constexpr int SMEM_TOTAL = 41984;

// Pre-converted W-hi (swizzled f16), written by prep kernel
__device__ __align__(16) uint32_t g_W16[8192];   // 32768 B

__device__ __forceinline__ uint32_t smem_u32(const void* p) {
    uint32_t a;
    asm("{ .reg .u64 t; cvta.to.shared.u64 t, %1; cvt.u32.u64 %0, t; }" : "=r"(a) : "l"(p));
    return a;
}
__device__ __forceinline__ uint32_t sw128(uint32_t off) { return off ^ ((off >> 3) & 0x70); }

__device__ __forceinline__ void ldsm_x4(uint32_t* r, uint32_t addr) {
    asm volatile("ldmatrix.sync.aligned.m8n8.x4.shared.b16 {%0,%1,%2,%3}, [%4];"
                 : "=r"(r[0]), "=r"(r[1]), "=r"(r[2]), "=r"(r[3]) : "r"(addr));
}
__device__ __forceinline__ void mma16816(float* c, const uint32_t* a, const uint32_t* b) {
    asm volatile("mma.sync.aligned.m16n8k16.row.col.f32.f16.f16.f32 "
                 "{%0,%1,%2,%3}, {%4,%5,%6,%7}, {%8,%9}, {%0,%1,%2,%3};"
                 : "+f"(c[0]), "+f"(c[1]), "+f"(c[2]), "+f"(c[3])
                 : "r"(a[0]), "r"(a[1]), "r"(a[2]), "r"(a[3]), "r"(b[0]), "r"(b[1]));
}

// float2 -> packed f16 hi pair + scaled f16 lo pair
__device__ __forceinline__ void cvt2(float a, float b, uint32_t& hi, uint32_t& lo) {
    __half2 hh = __floats2half2_rn(a, b);
    float2 bk = __half22float2(hh);
    __half2 ll = __floats2half2_rn((a - bk.x) * LO_SCALE, (b - bk.y) * LO_SCALE);
    hi = reinterpret_cast<uint32_t&>(hh);
    lo = reinterpret_cast<uint32_t&>(ll);
}

// Reference-order dot: single fp32 FMA chain, ascending k.
__device__ __forceinline__ float dot_seq(const float* __restrict__ Vrow,
                                         const float* __restrict__ Wrow) {
    float acc = 0.0f;
    #pragma unroll
    for (int q = 0; q < 16; q++) {
        float4 v = __ldg(reinterpret_cast<const float4*>(Vrow) + q);
        float4 w = __ldg(reinterpret_cast<const float4*>(Wrow) + q);
        acc = __fmaf_rn(v.x, w.x, acc);
        acc = __fmaf_rn(v.y, w.y, acc);
        acc = __fmaf_rn(v.z, w.z, acc);
        acc = __fmaf_rn(v.w, w.w, acc);
    }
    return acc;
}

// value -> sortable key with (255-h) embedded in low 8 mantissa bits
__device__ __forceinline__ float make_key(float v, int h) {
    uint32_t b = (__float_as_uint(v) & 0xFFFFFF00u) | (uint32_t)(255 - h);
    return __uint_as_float(b);
}
__device__ __forceinline__ int key_h(float k) {
    return 255 - (int)(__float_as_uint(k) & 0xFFu);
}

// ---- prep: convert W to swizzled f16-hi once ----
__global__ void prep_W_kernel(const float* __restrict__ W) {
    const int r = threadIdx.x;            // 256 threads, one W row each
    float f[8];
    #pragma unroll 1
    for (int q = 0; q < 8; q++) {
        *reinterpret_cast<float4*>(f)     = __ldg(reinterpret_cast<const float4*>(W + r * NI) + 2 * q);
        *reinterpret_cast<float4*>(f + 4) = __ldg(reinterpret_cast<const float4*>(W + r * NI) + 2 * q + 1);
        uint4 hi; uint32_t dummy;
        cvt2(f[0], f[1], hi.x, dummy);
        cvt2(f[2], f[3], hi.y, dummy);
        cvt2(f[4], f[5], hi.z, dummy);
        cvt2(f[6], f[7], hi.w, dummy);
        const uint32_t off = sw128((uint32_t)r * 128 + q * 16);
        *reinterpret_cast<uint4*>(reinterpret_cast<char*>(g_W16) + off) = hi;
    }
}

__global__ __launch_bounds__(256, 2)
void rochet_mma_kernel(const float* __restrict__ V,
                       const float* __restrict__ W,
                       const float* __restrict__ w0,
                       float* __restrict__ alloc_out,
                       float* __restrict__ pay_out,
                       int B)
{
    extern __shared__ char smem[];
    const uint32_t sbase = smem_u32(smem);
    const int tid = threadIdx.x;
    const int w   = tid >> 5;         // 8 warps
    const int l   = tid & 31;
    float* w0s = reinterpret_cast<float*>(smem + OFF_W0);

    // ---- stage W-hi (pre-converted + swizzled) and w0 ----
    {
        const uint4* src = reinterpret_cast<const uint4*>(g_W16);
        uint4* dst = reinterpret_cast<uint4*>(smem + OFF_WH);
        #pragma unroll
        for (int i = 0; i < 8; i++) dst[tid + 256 * i] = src[tid + 256 * i];
        w0s[tid] = w0[tid];
    }

    // ---- build A fragments directly from gmem: 2 mtiles (32 rows/warp) ----
    const long long base = (long long)blockIdx.x * TM;
    uint32_t ah[2][4][4], al[2][4][4];
    {
        const int r0 = w * 32 + (l >> 2);
        const int k0 = (l & 3) * 2;
        #pragma unroll
        for (int mt = 0; mt < 2; mt++)
            #pragma unroll
            for (int j = 0; j < 4; j++) {
                const long long row = base + r0 + mt * 16 + (j & 1) * 8;
                const int kb = k0 + (j >> 1) * 8;
                if (row < (long long)B) {
                    const float2* p = reinterpret_cast<const float2*>(V + row * NI + kb);
                    #pragma unroll
                    for (int ks = 0; ks < 4; ks++) {
                        const float2 v = __ldg(p + ks * 8);   // +16 floats per kstep
                        cvt2(v.x, v.y, ah[mt][ks][j], al[mt][ks][j]);
                    }
                } else {
                    #pragma unroll
                    for (int ks = 0; ks < 4; ks++) { ah[mt][ks][j] = 0u; al[mt][ks][j] = 0u; }
                }
            }
    }
    __syncthreads();

    // ---- main loop over 32 n-tiles ----
    float m1[4], m2[4];
    #pragma unroll
    for (int t = 0; t < 4; t++) { m1[t] = -3.4e38f; m2[t] = -3.4e38f; }

    // ldsm_x4 lane map: frag pairs cover k-steps kp*2 and kp*2+1
    const uint32_t bro4 = (uint32_t)(l & 7) * 128 + (uint32_t)((l >> 3) & 3) * 16;
    const int colb = 2 * (l & 3);

    #pragma unroll 2
    for (int nt = 0; nt < 32; nt++) {
        uint32_t bh[4][2];
        #pragma unroll
        for (int kp = 0; kp < 2; kp++) {
            const uint32_t off = sw128((uint32_t)nt * 1024 + bro4 + kp * 64);
            uint32_t rh[4];
            ldsm_x4(rh, sbase + OFF_WH + off);
            bh[2*kp][0]   = rh[0]; bh[2*kp][1]   = rh[1];
            bh[2*kp+1][0] = rh[2]; bh[2*kp+1][1] = rh[3];
        }
        const int hbase = nt * 8 + colb;
        const float2 w0p = *reinterpret_cast<const float2*>(smem + OFF_W0 + hbase * 4);

        #pragma unroll
        for (int mt = 0; mt < 2; mt++) {
            float c[4] = {0.f, 0.f, 0.f, 0.f};
            float d[4] = {0.f, 0.f, 0.f, 0.f};
            #pragma unroll
            for (int ks = 0; ks < 4; ks++) mma16816(c, ah[mt][ks], bh[ks]);
            #pragma unroll
            for (int ks = 0; ks < 4; ks++) mma16816(d, al[mt][ks], bh[ks]);

            const float k0 = make_key(__fmaf_rn(LO_INV, d[0], c[0]) + w0p.x, hbase);
            const float k1 = make_key(__fmaf_rn(LO_INV, d[1], c[1]) + w0p.y, hbase + 1);
            const float k2 = make_key(__fmaf_rn(LO_INV, d[2], c[2]) + w0p.x, hbase);
            const float k3 = make_key(__fmaf_rn(LO_INV, d[3], c[3]) + w0p.y, hbase + 1);
            const int s0 = 2 * mt, s1 = 2 * mt + 1;
            float t0 = fminf(m1[s0], k0); m1[s0] = fmaxf(m1[s0], k0); m2[s0] = fmaxf(m2[s0], t0);
            float t1 = fminf(m1[s0], k1); m1[s0] = fmaxf(m1[s0], k1); m2[s0] = fmaxf(m2[s0], t1);
            float t2 = fminf(m1[s1], k2); m1[s1] = fmaxf(m1[s1], k2); m2[s1] = fmaxf(m2[s1], t2);
            float t3 = fminf(m1[s1], k3); m1[s1] = fmaxf(m1[s1], k3); m2[s1] = fmaxf(m2[s1], t3);
        }
    }

    // ---- publish per-lane top-2 keys: cand[row_in_cta][l&3] ----
    #pragma unroll
    for (int mt = 0; mt < 2; mt++)
        #pragma unroll
        for (int rh = 0; rh < 2; rh++) {
            const int rc = w * 32 + mt * 16 + rh * 8 + (l >> 2);
            const int st = 2 * mt + rh;
            float2 pk = make_float2(m1[st], m2[st]);
            *reinterpret_cast<float2*>(smem + OFF_CAND + (rc * 4 + (l & 3)) * 8) = pk;
        }
    __syncwarp();

    // ---- epilogue: thread tid handles row tid (same warp wrote its cand) ----
    const long long row = base + tid;
    if (row < (long long)B) {
        float ck[8];
        #pragma unroll
        for (int q = 0; q < 4; q++) {
            const float2 pk = *reinterpret_cast<const float2*>(smem + OFF_CAND + (tid * 4 + q) * 8);
            ck[2 * q] = pk.x; ck[2 * q + 1] = pk.y;
        }
        float kbest = ck[0];
        #pragma unroll
        for (int q = 1; q < 8; q++) kbest = fmaxf(kbest, ck[q]);
        const int h1 = key_h(kbest);

        const float* Vrow = V + row * NI;
        float bestdot = dot_seq(Vrow, W + h1 * NI);
        float best = bestdot + w0s[h1];
        int bi = h1;
        const float thr = kbest - ARB_EPS;
        #pragma unroll 1
        for (int q = 0; q < 8; q++) {
            const int hq = key_h(ck[q]);
            if (ck[q] >= thr && hq != h1) {
                const float dd = dot_seq(Vrow, W + hq * NI);
                const float s = dd + w0s[hq];
                if (s > best || (s == best && hq < bi)) { best = s; bi = hq; bestdot = dd; }
            }
        }

        float* orow = alloc_out + row * NI;
        if (best > 0.0f) {
            const float4* wr = reinterpret_cast<const float4*>(W + bi * NI);
            #pragma unroll
            for (int q = 0; q < 16; q++) {
                float4 wv = __ldg(wr + q);
                wv.x = fminf(fmaxf(wv.x, 0.f), 1.f);
                wv.y = fminf(fmaxf(wv.y, 0.f), 1.f);
                wv.z = fminf(fmaxf(wv.z, 0.f), 1.f);
                wv.w = fminf(fmaxf(wv.w, 0.f), 1.f);
                reinterpret_cast<float4*>(orow)[q] = wv;
            }
            const float p = bestdot - best;
            pay_out[row] = p > 0.0f ? p : 0.0f;
        } else {
            const float4 z = make_float4(0.f, 0.f, 0.f, 0.f);
            #pragma unroll
            for (int q = 0; q < 16; q++) reinterpret_cast<float4*>(orow)[q] = z;
            pay_out[row] = 0.0f;
        }
    }
}

extern "C" void kernel_launch(void* const* d_in, const int* in_sizes, int n_in,
                              void* d_out, int out_size)
{
    const float* V  = (const float*)d_in[0];   // [B, 64]
    const float* W  = (const float*)d_in[1];   // [256, 64]
    const float* w0 = (const float*)d_in[2];   // [256]
    const int B = in_sizes[0] / NI;

    float* alloc_out = (float*)d_out;                          // [B, 64]
    float* pay_out   = (float*)d_out + (long long)B * NI;      // [B]

    cudaFuncSetAttribute(rochet_mma_kernel,
                         cudaFuncAttributeMaxDynamicSharedMemorySize, SMEM_TOTAL);

    prep_W_kernel<<<1, 256>>>(W);
    const int grid = (B + TM - 1) / TM;
    rochet_mma_kernel<<<grid, 256, SMEM_TOTAL>>>(V, W, w0, alloc_out, pay_out, B);
}

// round 14
// speedup vs baseline: 1.4682x; 1.0284x over previous
#include <cuda_runtime.h>
#include <cuda_fp16.h>
#include <cstdint>

static constexpr int NI = 64;     // items (K)
static constexpr int NH = 256;    // hidden units (N)
static constexpr int TM = 256;    // rows per block (8 warps x 32 rows)
#define ARB_EPS  4e-3f
#define LO_SCALE 2048.0f
#define LO_INV   4.8828125e-4f    // 2^-11

// ---- smem layout (bytes) ----
static constexpr int OFF_WH   = 0;       // 256 x 64 f16 swizzled = 32768
static constexpr int OFF_W0   = 32768;   // 256 f32               = 1024
static constexpr int OFF_CAND = 33792;   // 256 rows x 4 x 8B     = 8192
static constexpr int OFF_RESI = 41984;   // 256 int               = 1024
static constexpr int OFF_RESP = 43008;   // 256 f32               = 1024
static constexpr int SMEM_TOTAL = 44032;

// Pre-converted W-hi (swizzled f16), written by prep kernel
__device__ __align__(16) uint32_t g_W16[8192];   // 32768 B

__device__ __forceinline__ uint32_t smem_u32(const void* p) {
    uint32_t a;
    asm("{ .reg .u64 t; cvta.to.shared.u64 t, %1; cvt.u32.u64 %0, t; }" : "=r"(a) : "l"(p));
    return a;
}
__device__ __forceinline__ uint32_t sw128(uint32_t off) { return off ^ ((off >> 3) & 0x70); }

__device__ __forceinline__ void ldsm_x4(uint32_t* r, uint32_t addr) {
    asm volatile("ldmatrix.sync.aligned.m8n8.x4.shared.b16 {%0,%1,%2,%3}, [%4];"
                 : "=r"(r[0]), "=r"(r[1]), "=r"(r[2]), "=r"(r[3]) : "r"(addr));
}
__device__ __forceinline__ void mma16816(float* c, const uint32_t* a, const uint32_t* b) {
    asm volatile("mma.sync.aligned.m16n8k16.row.col.f32.f16.f16.f32 "
                 "{%0,%1,%2,%3}, {%4,%5,%6,%7}, {%8,%9}, {%0,%1,%2,%3};"
                 : "+f"(c[0]), "+f"(c[1]), "+f"(c[2]), "+f"(c[3])
                 : "r"(a[0]), "r"(a[1]), "r"(a[2]), "r"(a[3]), "r"(b[0]), "r"(b[1]));
}

// float2 -> packed f16 hi pair + scaled f16 lo pair
__device__ __forceinline__ void cvt2(float a, float b, uint32_t& hi, uint32_t& lo) {
    __half2 hh = __floats2half2_rn(a, b);
    float2 bk = __half22float2(hh);
    __half2 ll = __floats2half2_rn((a - bk.x) * LO_SCALE, (b - bk.y) * LO_SCALE);
    hi = reinterpret_cast<uint32_t&>(hh);
    lo = reinterpret_cast<uint32_t&>(ll);
}

// Reference-order dot: single fp32 FMA chain, ascending k.
__device__ __forceinline__ float dot_seq(const float* __restrict__ Vrow,
                                         const float* __restrict__ Wrow) {
    float acc = 0.0f;
    #pragma unroll
    for (int q = 0; q < 16; q++) {
        float4 v = __ldg(reinterpret_cast<const float4*>(Vrow) + q);
        float4 w = __ldg(reinterpret_cast<const float4*>(Wrow) + q);
        acc = __fmaf_rn(v.x, w.x, acc);
        acc = __fmaf_rn(v.y, w.y, acc);
        acc = __fmaf_rn(v.z, w.z, acc);
        acc = __fmaf_rn(v.w, w.w, acc);
    }
    return acc;
}

// value -> sortable key with (255-h) embedded in low 8 mantissa bits
__device__ __forceinline__ float make_key(float v, int h) {
    uint32_t b = (__float_as_uint(v) & 0xFFFFFF00u) | (uint32_t)(255 - h);
    return __uint_as_float(b);
}
__device__ __forceinline__ int key_h(float k) {
    return 255 - (int)(__float_as_uint(k) & 0xFFu);
}

// ---- prep: convert W to swizzled f16-hi once ----
__global__ void prep_W_kernel(const float* __restrict__ W) {
    const int r = threadIdx.x;            // 256 threads, one W row each
    float f[8];
    #pragma unroll 1
    for (int q = 0; q < 8; q++) {
        *reinterpret_cast<float4*>(f)     = __ldg(reinterpret_cast<const float4*>(W + r * NI) + 2 * q);
        *reinterpret_cast<float4*>(f + 4) = __ldg(reinterpret_cast<const float4*>(W + r * NI) + 2 * q + 1);
        uint4 hi; uint32_t dummy;
        cvt2(f[0], f[1], hi.x, dummy);
        cvt2(f[2], f[3], hi.y, dummy);
        cvt2(f[4], f[5], hi.z, dummy);
        cvt2(f[6], f[7], hi.w, dummy);
        const uint32_t off = sw128((uint32_t)r * 128 + q * 16);
        *reinterpret_cast<uint4*>(reinterpret_cast<char*>(g_W16) + off) = hi;
    }
}

__global__ __launch_bounds__(256, 2)
void rochet_mma_kernel(const float* __restrict__ V,
                       const float* __restrict__ W,
                       const float* __restrict__ w0,
                       float* __restrict__ alloc_out,
                       float* __restrict__ pay_out,
                       int B)
{
    extern __shared__ char smem[];
    const uint32_t sbase = smem_u32(smem);
    const int tid = threadIdx.x;
    const int w   = tid >> 5;         // 8 warps
    const int l   = tid & 31;
    float* w0s  = reinterpret_cast<float*>(smem + OFF_W0);
    int*   resI = reinterpret_cast<int*>(smem + OFF_RESI);
    float* resP = reinterpret_cast<float*>(smem + OFF_RESP);

    // ---- stage W-hi (pre-converted + swizzled) and w0 ----
    {
        const uint4* src = reinterpret_cast<const uint4*>(g_W16);
        uint4* dst = reinterpret_cast<uint4*>(smem + OFF_WH);
        #pragma unroll
        for (int i = 0; i < 8; i++) dst[tid + 256 * i] = src[tid + 256 * i];
        w0s[tid] = w0[tid];
    }

    // ---- build A fragments directly from gmem: 2 mtiles (32 rows/warp) ----
    const long long base = (long long)blockIdx.x * TM;
    uint32_t ah[2][4][4], al[2][4][4];
    {
        const int r0 = w * 32 + (l >> 2);
        const int k0 = (l & 3) * 2;
        #pragma unroll
        for (int mt = 0; mt < 2; mt++)
            #pragma unroll
            for (int j = 0; j < 4; j++) {
                const long long row = base + r0 + mt * 16 + (j & 1) * 8;
                const int kb = k0 + (j >> 1) * 8;
                if (row < (long long)B) {
                    const float2* p = reinterpret_cast<const float2*>(V + row * NI + kb);
                    #pragma unroll
                    for (int ks = 0; ks < 4; ks++) {
                        const float2 v = __ldg(p + ks * 8);   // +16 floats per kstep
                        cvt2(v.x, v.y, ah[mt][ks][j], al[mt][ks][j]);
                    }
                } else {
                    #pragma unroll
                    for (int ks = 0; ks < 4; ks++) { ah[mt][ks][j] = 0u; al[mt][ks][j] = 0u; }
                }
            }
    }
    __syncthreads();

    // ---- main loop over 32 n-tiles ----
    float m1[4], m2[4];
    #pragma unroll
    for (int t = 0; t < 4; t++) { m1[t] = -3.4e38f; m2[t] = -3.4e38f; }

    const uint32_t bro4 = (uint32_t)(l & 7) * 128 + (uint32_t)((l >> 3) & 3) * 16;
    const int colb = 2 * (l & 3);

    #pragma unroll 2
    for (int nt = 0; nt < 32; nt++) {
        uint32_t bh[4][2];
        #pragma unroll
        for (int kp = 0; kp < 2; kp++) {
            const uint32_t off = sw128((uint32_t)nt * 1024 + bro4 + kp * 64);
            uint32_t rh[4];
            ldsm_x4(rh, sbase + OFF_WH + off);
            bh[2*kp][0]   = rh[0]; bh[2*kp][1]   = rh[1];
            bh[2*kp+1][0] = rh[2]; bh[2*kp+1][1] = rh[3];
        }
        const int hbase = nt * 8 + colb;
        const float2 w0p = *reinterpret_cast<const float2*>(smem + OFF_W0 + hbase * 4);

        #pragma unroll
        for (int mt = 0; mt < 2; mt++) {
            float c[4] = {0.f, 0.f, 0.f, 0.f};
            float d[4] = {0.f, 0.f, 0.f, 0.f};
            #pragma unroll
            for (int ks = 0; ks < 4; ks++) mma16816(c, ah[mt][ks], bh[ks]);
            #pragma unroll
            for (int ks = 0; ks < 4; ks++) mma16816(d, al[mt][ks], bh[ks]);

            const float k0 = make_key(__fmaf_rn(LO_INV, d[0], c[0]) + w0p.x, hbase);
            const float k1 = make_key(__fmaf_rn(LO_INV, d[1], c[1]) + w0p.y, hbase + 1);
            const float k2 = make_key(__fmaf_rn(LO_INV, d[2], c[2]) + w0p.x, hbase);
            const float k3 = make_key(__fmaf_rn(LO_INV, d[3], c[3]) + w0p.y, hbase + 1);
            const int s0 = 2 * mt, s1 = 2 * mt + 1;
            float t0 = fminf(m1[s0], k0); m1[s0] = fmaxf(m1[s0], k0); m2[s0] = fmaxf(m2[s0], t0);
            float t1 = fminf(m1[s0], k1); m1[s0] = fmaxf(m1[s0], k1); m2[s0] = fmaxf(m2[s0], t1);
            float t2 = fminf(m1[s1], k2); m1[s1] = fmaxf(m1[s1], k2); m2[s1] = fmaxf(m2[s1], t2);
            float t3 = fminf(m1[s1], k3); m1[s1] = fmaxf(m1[s1], k3); m2[s1] = fmaxf(m2[s1], t3);
        }
    }

    // ---- publish per-lane top-2 keys: cand[row_in_cta][l&3] ----
    #pragma unroll
    for (int mt = 0; mt < 2; mt++)
        #pragma unroll
        for (int rh = 0; rh < 2; rh++) {
            const int rc = w * 32 + mt * 16 + rh * 8 + (l >> 2);
            const int st = 2 * mt + rh;
            float2 pk = make_float2(m1[st], m2[st]);
            *reinterpret_cast<float2*>(smem + OFF_CAND + (rc * 4 + (l & 3)) * 8) = pk;
        }
    __syncwarp();

    // ---- decide winner + payment for row tid ----
    {
        const long long row = base + tid;
        if (row < (long long)B) {
            float ck[8];
            #pragma unroll
            for (int q = 0; q < 4; q++) {
                const float2 pk = *reinterpret_cast<const float2*>(smem + OFF_CAND + (tid * 4 + q) * 8);
                ck[2 * q] = pk.x; ck[2 * q + 1] = pk.y;
            }
            float kbest = ck[0];
            #pragma unroll
            for (int q = 1; q < 8; q++) kbest = fmaxf(kbest, ck[q]);
            // second-best distinct key
            float ksec = -3.4e38f;
            #pragma unroll
            for (int q = 0; q < 8; q++) {
                const float c = (ck[q] == kbest) ? -3.4e38f : ck[q];
                ksec = fmaxf(ksec, c);
            }
            int bi = key_h(kbest);
            float pay;
            bool pos;
            if ((kbest - ksec) < ARB_EPS || fabsf(kbest) < ARB_EPS) {
                // rare: exact re-ranking with reference-order fp32
                const float* Vrow = V + row * NI;
                float bestdot = dot_seq(Vrow, W + bi * NI);
                float best = bestdot + w0s[bi];
                const float thr = kbest - ARB_EPS;
                #pragma unroll 1
                for (int q = 0; q < 8; q++) {
                    const int hq = key_h(ck[q]);
                    if (ck[q] >= thr && hq != bi) {
                        const float dd = dot_seq(Vrow, W + hq * NI);
                        const float s = dd + w0s[hq];
                        if (s > best || (s == best && hq < bi)) { best = s; bi = hq; bestdot = dd; }
                    }
                }
                pos = best > 0.0f;
                const float p = bestdot - best;
                pay = p > 0.0f ? p : 0.0f;
            } else {
                pos = kbest > 0.0f;
                const float p = -w0s[bi];
                pay = p > 0.0f ? p : 0.0f;
            }
            resI[tid] = pos ? bi : -1;
            resP[tid] = pos ? pay : 0.0f;
        }
    }
    __syncthreads();

    // ---- cooperative coalesced writer: 2 rows per warp-iteration ----
    {
        const int h16 = l >> 4;          // half-warp id
        const int l16 = l & 15;          // lane within half-warp
        #pragma unroll 1
        for (int it = 0; it < 16; it++) {
            const int rc = w * 32 + it * 2 + h16;
            const long long row = base + rc;
            if (row >= (long long)B) continue;
            const int bi = resI[rc];
            if (l16 == 0) pay_out[row] = resP[rc];
            float4 wv;
            if (bi >= 0) {
                wv = __ldg(reinterpret_cast<const float4*>(W + bi * NI) + l16);
                wv.x = fminf(fmaxf(wv.x, 0.f), 1.f);
                wv.y = fminf(fmaxf(wv.y, 0.f), 1.f);
                wv.z = fminf(fmaxf(wv.z, 0.f), 1.f);
                wv.w = fminf(fmaxf(wv.w, 0.f), 1.f);
            } else {
                wv = make_float4(0.f, 0.f, 0.f, 0.f);
            }
            reinterpret_cast<float4*>(alloc_out + row * NI)[l16] = wv;
        }
    }
}

extern "C" void kernel_launch(void* const* d_in, const int* in_sizes, int n_in,
                              void* d_out, int out_size)
{
    const float* V  = (const float*)d_in[0];   // [B, 64]
    const float* W  = (const float*)d_in[1];   // [256, 64]
    const float* w0 = (const float*)d_in[2];   // [256]
    const int B = in_sizes[0] / NI;

    float* alloc_out = (float*)d_out;                          // [B, 64]
    float* pay_out   = (float*)d_out + (long long)B * NI;      // [B]

    cudaFuncSetAttribute(rochet_mma_kernel,
                         cudaFuncAttributeMaxDynamicSharedMemorySize, SMEM_TOTAL);

    prep_W_kernel<<<1, 256>>>(W);
    const int grid = (B + TM - 1) / TM;
    rochet_mma_kernel<<<grid, 256, SMEM_TOTAL>>>(V, W, w0, alloc_out, pay_out, B);
}

// round 16
// speedup vs baseline: 2.1684x; 1.4769x over previous
#include <cuda_runtime.h>
#include <cuda_fp16.h>
#include <cstdint>

static constexpr int NI = 64;     // items (K)
static constexpr int NH = 256;    // hidden units (N)
static constexpr int TM = 256;    // rows per block (8 warps x 32 rows)
#define ARB_EPS  4e-3f
#define LO_SCALE 2048.0f
#define LO_INV   4.8828125e-4f    // 2^-11

// ---- smem layout (bytes) ----
static constexpr int OFF_WH   = 0;       // 256 x 64 f16 swizzled = 32768
static constexpr int OFF_W0   = 32768;   // 256 f32               = 1024
static constexpr int OFF_CAND = 33792;   // 256 rows x 4 x 8B     = 8192
static constexpr int OFF_RESI = 41984;   // 256 int               = 1024
static constexpr int OFF_RESP = 43008;   // 256 f32               = 1024
static constexpr int SMEM_TOTAL = 44032;

// Pre-converted W-hi (swizzled f16) + pre-clamped W (f32), written by prep kernel
__device__ __align__(16) uint32_t g_W16[8192];     // 32768 B
__device__ __align__(16) float    g_Wc[NH * NI];   // 65536 B

__device__ __forceinline__ uint32_t smem_u32(const void* p) {
    uint32_t a;
    asm("{ .reg .u64 t; cvta.to.shared.u64 t, %1; cvt.u32.u64 %0, t; }" : "=r"(a) : "l"(p));
    return a;
}
__device__ __forceinline__ uint32_t sw128(uint32_t off) { return off ^ ((off >> 3) & 0x70); }

__device__ __forceinline__ void ldsm_x4(uint32_t* r, uint32_t addr) {
    asm volatile("ldmatrix.sync.aligned.m8n8.x4.shared.b16 {%0,%1,%2,%3}, [%4];"
                 : "=r"(r[0]), "=r"(r[1]), "=r"(r[2]), "=r"(r[3]) : "r"(addr));
}
__device__ __forceinline__ void mma16816(float* c, const uint32_t* a, const uint32_t* b) {
    asm volatile("mma.sync.aligned.m16n8k16.row.col.f32.f16.f16.f32 "
                 "{%0,%1,%2,%3}, {%4,%5,%6,%7}, {%8,%9}, {%0,%1,%2,%3};"
                 : "+f"(c[0]), "+f"(c[1]), "+f"(c[2]), "+f"(c[3])
                 : "r"(a[0]), "r"(a[1]), "r"(a[2]), "r"(a[3]), "r"(b[0]), "r"(b[1]));
}

// float2 -> packed f16 hi pair + scaled f16 lo pair
__device__ __forceinline__ void cvt2(float a, float b, uint32_t& hi, uint32_t& lo) {
    __half2 hh = __floats2half2_rn(a, b);
    float2 bk = __half22float2(hh);
    __half2 ll = __floats2half2_rn((a - bk.x) * LO_SCALE, (b - bk.y) * LO_SCALE);
    hi = reinterpret_cast<uint32_t&>(hh);
    lo = reinterpret_cast<uint32_t&>(ll);
}

// Reference-order dot: single fp32 FMA chain, ascending k.
__device__ __forceinline__ float dot_seq(const float* __restrict__ Vrow,
                                         const float* __restrict__ Wrow) {
    float acc = 0.0f;
    #pragma unroll
    for (int q = 0; q < 16; q++) {
        float4 v = __ldg(reinterpret_cast<const float4*>(Vrow) + q);
        float4 w = __ldg(reinterpret_cast<const float4*>(Wrow) + q);
        acc = __fmaf_rn(v.x, w.x, acc);
        acc = __fmaf_rn(v.y, w.y, acc);
        acc = __fmaf_rn(v.z, w.z, acc);
        acc = __fmaf_rn(v.w, w.w, acc);
    }
    return acc;
}

// value -> sortable key with (255-h) embedded in low 8 mantissa bits
__device__ __forceinline__ float make_key(float v, int h) {
    uint32_t b = (__float_as_uint(v) & 0xFFFFFF00u) | (uint32_t)(255 - h);
    return __uint_as_float(b);
}
__device__ __forceinline__ int key_h(float k) {
    return 255 - (int)(__float_as_uint(k) & 0xFFu);
}

// ---- prep: convert W to swizzled f16-hi + clamped f32 copy, once ----
__global__ void prep_W_kernel(const float* __restrict__ W) {
    const int r = threadIdx.x;            // 256 threads, one W row each
    float f[8];
    #pragma unroll 1
    for (int q = 0; q < 8; q++) {
        float4 f0 = __ldg(reinterpret_cast<const float4*>(W + r * NI) + 2 * q);
        float4 f1 = __ldg(reinterpret_cast<const float4*>(W + r * NI) + 2 * q + 1);
        *reinterpret_cast<float4*>(f)     = f0;
        *reinterpret_cast<float4*>(f + 4) = f1;
        uint4 hi; uint32_t dummy;
        cvt2(f[0], f[1], hi.x, dummy);
        cvt2(f[2], f[3], hi.y, dummy);
        cvt2(f[4], f[5], hi.z, dummy);
        cvt2(f[6], f[7], hi.w, dummy);
        const uint32_t off = sw128((uint32_t)r * 128 + q * 16);
        *reinterpret_cast<uint4*>(reinterpret_cast<char*>(g_W16) + off) = hi;
        // clamped copy
        f0.x = fminf(fmaxf(f0.x, 0.f), 1.f); f0.y = fminf(fmaxf(f0.y, 0.f), 1.f);
        f0.z = fminf(fmaxf(f0.z, 0.f), 1.f); f0.w = fminf(fmaxf(f0.w, 0.f), 1.f);
        f1.x = fminf(fmaxf(f1.x, 0.f), 1.f); f1.y = fminf(fmaxf(f1.y, 0.f), 1.f);
        f1.z = fminf(fmaxf(f1.z, 0.f), 1.f); f1.w = fminf(fmaxf(f1.w, 0.f), 1.f);
        reinterpret_cast<float4*>(g_Wc + r * NI)[2 * q]     = f0;
        reinterpret_cast<float4*>(g_Wc + r * NI)[2 * q + 1] = f1;
    }
}

__global__ __launch_bounds__(256, 2)
void rochet_mma_kernel(const float* __restrict__ V,
                       const float* __restrict__ W,
                       const float* __restrict__ w0,
                       float* __restrict__ alloc_out,
                       float* __restrict__ pay_out,
                       int B)
{
    extern __shared__ char smem[];
    const uint32_t sbase = smem_u32(smem);
    const int tid = threadIdx.x;
    const int w   = tid >> 5;         // 8 warps
    const int l   = tid & 31;
    float* w0s  = reinterpret_cast<float*>(smem + OFF_W0);
    int*   resI = reinterpret_cast<int*>(smem + OFF_RESI);
    float* resP = reinterpret_cast<float*>(smem + OFF_RESP);

    // ---- stage W-hi (pre-converted + swizzled) and w0 ----
    {
        const uint4* src = reinterpret_cast<const uint4*>(g_W16);
        uint4* dst = reinterpret_cast<uint4*>(smem + OFF_WH);
        #pragma unroll
        for (int i = 0; i < 8; i++) dst[tid + 256 * i] = src[tid + 256 * i];
        w0s[tid] = w0[tid];
    }

    // ---- build A fragments directly from gmem: 2 mtiles (32 rows/warp) ----
    const long long base = (long long)blockIdx.x * TM;
    uint32_t ah[2][4][4], al[2][4][4];
    {
        const int r0 = w * 32 + (l >> 2);
        const int k0 = (l & 3) * 2;
        #pragma unroll
        for (int mt = 0; mt < 2; mt++)
            #pragma unroll
            for (int j = 0; j < 4; j++) {
                const long long row = base + r0 + mt * 16 + (j & 1) * 8;
                const int kb = k0 + (j >> 1) * 8;
                if (row < (long long)B) {
                    const float2* p = reinterpret_cast<const float2*>(V + row * NI + kb);
                    #pragma unroll
                    for (int ks = 0; ks < 4; ks++) {
                        const float2 v = __ldg(p + ks * 8);   // +16 floats per kstep
                        cvt2(v.x, v.y, ah[mt][ks][j], al[mt][ks][j]);
                    }
                } else {
                    #pragma unroll
                    for (int ks = 0; ks < 4; ks++) { ah[mt][ks][j] = 0u; al[mt][ks][j] = 0u; }
                }
            }
    }
    __syncthreads();

    // ---- main loop over 32 n-tiles ----
    float m1[4], m2[4];
    #pragma unroll
    for (int t = 0; t < 4; t++) { m1[t] = -3.4e38f; m2[t] = -3.4e38f; }

    const uint32_t bro4 = (uint32_t)(l & 7) * 128 + (uint32_t)((l >> 3) & 3) * 16;
    const int colb = 2 * (l & 3);

    #pragma unroll 4
    for (int nt = 0; nt < 32; nt++) {
        uint32_t bh[4][2];
        #pragma unroll
        for (int kp = 0; kp < 2; kp++) {
            const uint32_t off = sw128((uint32_t)nt * 1024 + bro4 + kp * 64);
            uint32_t rh[4];
            ldsm_x4(rh, sbase + OFF_WH + off);
            bh[2*kp][0]   = rh[0]; bh[2*kp][1]   = rh[1];
            bh[2*kp+1][0] = rh[2]; bh[2*kp+1][1] = rh[3];
        }
        const int hbase = nt * 8 + colb;
        const float2 w0p = *reinterpret_cast<const float2*>(smem + OFF_W0 + hbase * 4);

        #pragma unroll
        for (int mt = 0; mt < 2; mt++) {
            float c[4] = {0.f, 0.f, 0.f, 0.f};
            float d[4] = {0.f, 0.f, 0.f, 0.f};
            #pragma unroll
            for (int ks = 0; ks < 4; ks++) mma16816(c, ah[mt][ks], bh[ks]);
            #pragma unroll
            for (int ks = 0; ks < 4; ks++) mma16816(d, al[mt][ks], bh[ks]);

            const float k0 = make_key(__fmaf_rn(LO_INV, d[0], c[0]) + w0p.x, hbase);
            const float k1 = make_key(__fmaf_rn(LO_INV, d[1], c[1]) + w0p.y, hbase + 1);
            const float k2 = make_key(__fmaf_rn(LO_INV, d[2], c[2]) + w0p.x, hbase);
            const float k3 = make_key(__fmaf_rn(LO_INV, d[3], c[3]) + w0p.y, hbase + 1);
            const int s0 = 2 * mt, s1 = 2 * mt + 1;
            float t0 = fminf(m1[s0], k0); m1[s0] = fmaxf(m1[s0], k0); m2[s0] = fmaxf(m2[s0], t0);
            float t1 = fminf(m1[s0], k1); m1[s0] = fmaxf(m1[s0], k1); m2[s0] = fmaxf(m2[s0], t1);
            float t2 = fminf(m1[s1], k2); m1[s1] = fmaxf(m1[s1], k2); m2[s1] = fmaxf(m2[s1], t2);
            float t3 = fminf(m1[s1], k3); m1[s1] = fmaxf(m1[s1], k3); m2[s1] = fmaxf(m2[s1], t3);
        }
    }

    // ---- publish per-lane top-2 keys: cand[row_in_cta][l&3] ----
    #pragma unroll
    for (int mt = 0; mt < 2; mt++)
        #pragma unroll
        for (int rh = 0; rh < 2; rh++) {
            const int rc = w * 32 + mt * 16 + rh * 8 + (l >> 2);
            const int st = 2 * mt + rh;
            float2 pk = make_float2(m1[st], m2[st]);
            *reinterpret_cast<float2*>(smem + OFF_CAND + (rc * 4 + (l & 3)) * 8) = pk;
        }
    __syncwarp();

    // ---- decide winner + payment for row tid ----
    {
        const long long row = base + tid;
        if (row < (long long)B) {
            float ck[8];
            #pragma unroll
            for (int q = 0; q < 4; q++) {
                const float2 pk = *reinterpret_cast<const float2*>(smem + OFF_CAND + (tid * 4 + q) * 8);
                ck[2 * q] = pk.x; ck[2 * q + 1] = pk.y;
            }
            float kbest = ck[0];
            #pragma unroll
            for (int q = 1; q < 8; q++) kbest = fmaxf(kbest, ck[q]);
            // second-best distinct key
            float ksec = -3.4e38f;
            #pragma unroll
            for (int q = 0; q < 8; q++) {
                const float c = (ck[q] == kbest) ? -3.4e38f : ck[q];
                ksec = fmaxf(ksec, c);
            }
            int bi = key_h(kbest);
            float pay;
            bool pos;
            if ((kbest - ksec) < ARB_EPS || fabsf(kbest) < ARB_EPS) {
                // rare: exact re-ranking with reference-order fp32
                const float* Vrow = V + row * NI;
                float bestdot = dot_seq(Vrow, W + bi * NI);
                float best = bestdot + w0s[bi];
                const float thr = kbest - ARB_EPS;
                #pragma unroll 1
                for (int q = 0; q < 8; q++) {
                    const int hq = key_h(ck[q]);
                    if (ck[q] >= thr && hq != bi) {
                        const float dd = dot_seq(Vrow, W + hq * NI);
                        const float s = dd + w0s[hq];
                        if (s > best || (s == best && hq < bi)) { best = s; bi = hq; bestdot = dd; }
                    }
                }
                pos = best > 0.0f;
                const float p = bestdot - best;
                pay = p > 0.0f ? p : 0.0f;
            } else {
                pos = kbest > 0.0f;
                const float p = -w0s[bi];
                pay = p > 0.0f ? p : 0.0f;
            }
            resI[tid] = pos ? bi : -1;
            resP[tid] = pos ? pay : 0.0f;
        }
    }
    __syncthreads();

    // ---- cooperative coalesced writer: 2 rows per warp-iteration ----
    {
        const int h16 = l >> 4;          // half-warp id
        const int l16 = l & 15;          // lane within half-warp
        const float4* WcF4 = reinterpret_cast<const float4*>(g_Wc);
        #pragma unroll 1
        for (int it = 0; it < 16; it++) {
            const int rc = w * 32 + it * 2 + h16;
            const long long row = base + rc;
            if (row >= (long long)B) continue;
            const int bi = resI[rc];
            if (l16 == 0) pay_out[row] = resP[rc];
            float4 wv;
            if (bi >= 0) {
                wv = __ldg(WcF4 + bi * (NI / 4) + l16);   // pre-clamped
            } else {
                wv = make_float4(0.f, 0.f, 0.f, 0.f);
            }
            reinterpret_cast<float4*>(alloc_out + row * NI)[l16] = wv;
        }
    }
}

extern "C" void kernel_launch(void* const* d_in, const int* in_sizes, int n_in,
                              void* d_out, int out_size)
{
    const float* V  = (const float*)d_in[0];   // [B, 64]
    const float* W  = (const float*)d_in[1];   // [256, 64]
    const float* w0 = (const float*)d_in[2];   // [256]
    const int B = in_sizes[0] / NI;

    float* alloc_out = (float*)d_out;                          // [B, 64]
    float* pay_out   = (float*)d_out + (long long)B * NI;      // [B]

    cudaFuncSetAttribute(rochet_mma_kernel,
                         cudaFuncAttributeMaxDynamicSharedMemorySize, SMEM_TOTAL);

    prep_W_kernel<<<1, 256>>>(W);
    const int grid = (B + TM - 1) / TM;
    rochet_mma_kernel<<<grid, 256, SMEM_TOTAL>>>(V, W, w0, alloc_out, pay_out, B);
}